// round 9
// baseline (speedup 1.0000x reference)
#include <cuda_runtime.h>
#include <cstdint>

#define AN 200000
#define NCLS 20          // foreground classes (labels 1..20)
#define NBIN 256         // log-domain histogram bins
#define TOPK 400
#define TOPKP 416        // TOPK padded to word boundary (13*32)
#define SEL_CAP 4096
#define DET 200
#define NW 13            // ceil(TOPK/32)
#define NMS_T 0.45f
#define K2E 1.44269504088896f

// ---------------- scratch (static device globals; no allocation) -------------
__device__ unsigned           g_binsP[AN * 8];          // 20 bin bytes/anchor, 32B stride
__device__ int                g_hist[NCLS * NBIN];
__device__ int                g_cut[NCLS];              // widened cutoff bin (>=1)
__device__ unsigned           g_cutPack[5];             // cut bytes packed like bins
__device__ unsigned long long g_sel[NCLS * SEL_CAP];    // EXACT keys (scorebits<<32)|(~idx)
__device__ int                g_selCnt[NCLS];
__device__ unsigned long long g_kept[NCLS * DET];       // compacted post-NMS keys
__device__ float4             g_keptBox[NCLS * DET];
__device__ int                g_keptCnt[NCLS];

// ---------------- K1: log-domain bins + block-private histogram --------------
// bin = clamp((int)fmaf(log2(score), 38.2, 255.4), 0, 255); score 0.0099 -> ~1.
__global__ void __launch_bounds__(256) k_prep(const float* __restrict__ logits) {
    __shared__ int h[NCLS * NBIN];                     // 20KB private histogram
    int tid = threadIdx.x;
    for (int t = tid; t < NCLS * NBIN; t += 256) h[t] = 0;
    __syncthreads();

    int q = blockIdx.x * 256 + tid;                    // quad of 4 anchors
    if (q < AN / 4) {
        const float4* src = (const float4*)logits + (size_t)q * 21;  // 84 floats
        float S[4] = {0.f, 0.f, 0.f, 0.f};
#pragma unroll
        for (int k = 0; k < 21; k++) {
            float4 v = src[k];
            S[(4 * k + 0) / 21] += exp2f(v.x * K2E);
            S[(4 * k + 1) / 21] += exp2f(v.y * K2E);
            S[(4 * k + 2) / 21] += exp2f(v.z * K2E);
            S[(4 * k + 3) / 21] += exp2f(v.w * K2E);
        }
        float lg[4];
#pragma unroll
        for (int a = 0; a < 4; a++) lg[a] = __log2f(S[a]);

        unsigned w[20];
#pragma unroll
        for (int t = 0; t < 20; t++) w[t] = 0;
#pragma unroll
        for (int k = 0; k < 21; k++) {
            float4 v = src[k];                          // L1 hit (2nd pass)
            float e[4] = {v.x, v.y, v.z, v.w};
#pragma unroll
            for (int j = 0; j < 4; j++) {
                int f = 4 * k + j, a = f / 21, c = f % 21;
                if (c >= 1) {
                    int cc = c - 1;
                    float y = fmaf(e[j], K2E, -lg[a]);
                    int bin = (int)fmaf(y, 38.2f, 255.4f);
                    bin = max(0, min(255, bin));
                    if (bin > 0) atomicAdd(&h[cc * NBIN + bin], 1);
                    w[a * 5 + (cc >> 2)] |= (unsigned)bin << ((cc & 3) * 8);
                }
            }
        }
#pragma unroll
        for (int a = 0; a < 4; a++) {
            unsigned i = (unsigned)(q * 4 + a);
            *(uint4*)&g_binsP[(size_t)i * 8] =
                make_uint4(w[a * 5], w[a * 5 + 1], w[a * 5 + 2], w[a * 5 + 3]);
            g_binsP[(size_t)i * 8 + 4] = w[a * 5 + 4];
        }
    }
    __syncthreads();
    for (int t = tid; t < NCLS * NBIN; t += 256) {
        int v = h[t];
        if (v) atomicAdd(&g_hist[t], v);
    }
}

// ---------------- K2: widened rank-400 cutoff; then reset state --------------
__global__ void k_cut() {
    int tid = threadIdx.x, wid = tid >> 5, lane = tid & 31;
    for (int c = wid; c < NCLS; c += 8) {
        int cum = 0, cutbin = 1;
        bool found = false;
        for (int base = NBIN - 32; base >= 0; base -= 32) {
            int b = base + 31 - lane;                 // lane 0 = highest bin
            int v = g_hist[c * NBIN + b];
            int s = v;
#pragma unroll
            for (int off = 1; off < 32; off <<= 1) {
                int t = __shfl_up_sync(0xffffffffu, s, off);
                if (lane >= off) s += t;
            }
            unsigned bal = __ballot_sync(0xffffffffu, (cum + s) >= TOPK);
            int tot = __shfl_sync(0xffffffffu, s, 31);
            if (bal) {
                cutbin = base + 31 - (__ffs(bal) - 1);
                found = true;
                break;
            }
            cum += tot;
        }
        // widen by 1 bin: approx-score error (~1e-6) vs bin width (~1.8%) margin
        if (lane == 0) g_cut[c] = found ? max(cutbin - 1, 1) : 1;
    }
    __syncthreads();
    // reset for the NEXT call; selCnt consumed later in THIS call
    for (int t = tid; t < NCLS * NBIN; t += 256) g_hist[t] = 0;
    if (tid < NCLS) g_selCnt[tid] = 0;
    __syncthreads();
    if (tid < 5) {
        unsigned p = 0;
#pragma unroll
        for (int j = 0; j < 4; j++) {
            int c = tid * 4 + j;
            unsigned cv = (c < NCLS) ? (unsigned)g_cut[c] : 255u;
            p |= (cv & 255u) << (j * 8);
        }
        g_cutPack[tid] = p;
    }
}

// ---------------- K3: fused scan + exact rescoring (full parallelism) --------
__global__ void __launch_bounds__(256) k_scanexact(const float* __restrict__ logits) {
    __shared__ unsigned cp[5];
    __shared__ int scut[NCLS];
    if (threadIdx.x < 5) cp[threadIdx.x] = g_cutPack[threadIdx.x];
    if (threadIdx.x < NCLS) scut[threadIdx.x] = g_cut[threadIdx.x];
    __syncthreads();
    int i = blockIdx.x * 256 + threadIdx.x;
    if (i >= AN) return;
    uint4 b4 = *(const uint4*)&g_binsP[(size_t)i * 8];
    unsigned b5 = g_binsP[(size_t)i * 8 + 4];
    unsigned any = __vsetgeu4(b4.x, cp[0]) | __vsetgeu4(b4.y, cp[1]) |
                   __vsetgeu4(b4.z, cp[2]) | __vsetgeu4(b4.w, cp[3]) |
                   __vsetgeu4(b5, cp[4]);
    if (!any) return;

    unsigned wv[5] = {b4.x, b4.y, b4.z, b4.w, b5};
    // exact softmax pieces (accurate expf, div.rn) — matches reference path
    const float* L = logits + (size_t)i * 21;
    float Lr[21];
#pragma unroll
    for (int c = 0; c < 21; c++) Lr[c] = L[c];
    float m = Lr[0];
#pragma unroll
    for (int c = 1; c < 21; c++) m = fmaxf(m, Lr[c]);
    float S = 0.f;
#pragma unroll
    for (int c = 0; c < 21; c++) S += expf(Lr[c] - m);

#pragma unroll
    for (int c = 0; c < NCLS; c++) {
        int b = (wv[c >> 2] >> ((c & 3) * 8)) & 255;
        if (b < scut[c]) continue;
        float ex = expf(Lr[c + 1] - m) / S;            // exact, matches reference
        if (ex <= 0.01f) continue;
        unsigned long long key =
            ((unsigned long long)__float_as_uint(ex) << 32) | (0xFFFFFFFFu - (unsigned)i);
        int p = atomicAdd(&g_selCnt[c], 1);
        if (p < SEL_CAP) g_sel[c * SEL_CAP + p] = key;
    }
}

// ---------------- bitonic sort (descending) in shared ------------------------
__device__ void bitonic_desc(unsigned long long* buf, int np2) {
    int tid = threadIdx.x, bd = blockDim.x;
    for (int k = 2; k <= np2; k <<= 1) {
        for (int j = k >> 1; j > 0; j >>= 1) {
            for (int t = tid; t < np2; t += bd) {
                int ixj = t ^ j;
                if (ixj > t) {
                    unsigned long long a = buf[t], b = buf[ixj];
                    bool desc = ((t & k) == 0);
                    if ((a < b) == desc) { buf[t] = b; buf[ixj] = a; }
                }
            }
            __syncthreads();
        }
    }
}

// ---------------- K4: sort + decode + TASK-parallel bitmask NMS + compact ----
__global__ void __launch_bounds__(1024) k_sortnms(const float* __restrict__ reg,
                                                  const float* __restrict__ anc) {
    __shared__ unsigned long long buf[SEL_CAP];        // 32KB (keys; tail reused)
    __shared__ float X1[TOPKP], Y1[TOPKP], X2[TOPKP], Y2[TOPKP], AR[TOPKP];
    __shared__ unsigned supw[NW];
    unsigned* mask = (unsigned*)(buf + 512);           // overlay: keys live in [0,400)
    int c = blockIdx.x, tid = threadIdx.x, lane = tid & 31;
    int n = min(g_selCnt[c], SEL_CAP);
    int np2 = 2; while (np2 < n) np2 <<= 1;
    for (int t = tid; t < np2; t += blockDim.x)
        buf[t] = (t < n) ? g_sel[c * SEL_CAP + t] : 0ull;
    __syncthreads();
    bitonic_desc(buf, np2);
    int nn = min(n, TOPK);

    // decode top-nn; pad [nn, TOPKP) with degenerate zero boxes (IoU -> false)
    for (int t = tid; t < TOPKP; t += blockDim.x) {
        if (t < nn) {
            unsigned idx = 0xFFFFFFFFu - (unsigned)(buf[t] & 0xFFFFFFFFull);
            float4 a4 = *(const float4*)(anc + (size_t)idx * 4);
            float4 r4 = *(const float4*)(reg + (size_t)idx * 4);
            float aw = a4.z - a4.x, ah = a4.w - a4.y;
            float acx = a4.x + 0.5f * aw, acy = a4.y + 0.5f * ah;
            float dx = r4.x / 10.0f, dy = r4.y / 10.0f;
            float dw = fminf(r4.z / 5.0f, 4.135166556742356f);
            float dh = fminf(r4.w / 5.0f, 4.135166556742356f);
            float pcx = dx * aw + acx, pcy = dy * ah + acy;
            float pw = expf(dw) * aw, ph = expf(dh) * ah;
            float x1 = fminf(fmaxf(pcx - 0.5f * pw, 0.f), 320.f);
            float y1 = fminf(fmaxf(pcy - 0.5f * ph, 0.f), 320.f);
            float x2 = fminf(fmaxf(pcx + 0.5f * pw, 0.f), 320.f);
            float y2 = fminf(fmaxf(pcy + 0.5f * ph, 0.f), 320.f);
            X1[t] = x1; Y1[t] = y1; X2[t] = x2; Y2[t] = y2;
            AR[t] = (x2 - x1) * (y2 - y1);
        } else {
            X1[t] = 0.f; Y1[t] = 0.f; X2[t] = 0.f; Y2[t] = 0.f; AR[t] = 0.f;
        }
    }
    __syncthreads();

    // task-parallel mask build: task = (row i, word w); all 1024 threads busy
    int nw_used = (nn + 31) >> 5;
    int ntask = nn * nw_used;
    for (int task = tid; task < ntask; task += blockDim.x) {
        int i = task / nw_used, w = task - i * nw_used;
        int jbase = w << 5;
        unsigned m = 0;
        if (jbase + 31 > i) {                          // word touches j>i region
            float xi1 = X1[i], yi1 = Y1[i], xi2 = X2[i], yi2 = Y2[i], ai = AR[i];
#pragma unroll
            for (int b = 0; b < 32; b++) {             // branch-free: pad handles j>=nn
                int j = jbase + b;
                float lx = fmaxf(xi1, X1[j]), ly = fmaxf(yi1, Y1[j]);
                float rx = fminf(xi2, X2[j]), ry = fminf(yi2, Y2[j]);
                float ww = fmaxf(rx - lx, 0.f), hh = fmaxf(ry - ly, 0.f);
                float inter = ww * hh;
                float iou = inter / (ai + AR[j] - inter);   // div.rn; NaN>T==false
                if (iou > NMS_T) m |= (1u << b);
            }
            if (i >= jbase)                            // clear diagonal + below bits
                m &= ~(((i - jbase) >= 31) ? 0xFFFFFFFFu : ((2u << (i - jbase)) - 1u));
        }
        mask[i * NW + w] = m;
    }
    __syncthreads();

    if (tid < 32) {                                    // serial greedy sweep, prefetched
        unsigned sup = 0;
        bool act = (lane < nw_used);
        unsigned cur = (act && nn > 0) ? mask[lane] : 0u;
        for (int i = 0; i < nn; i++) {
            unsigned nxt = (act && i + 1 < nn) ? mask[(i + 1) * NW + lane] : 0u;
            unsigned wi = __shfl_sync(0xffffffff, sup, i >> 5);
            if (!((wi >> (i & 31)) & 1)) sup |= cur;
            cur = nxt;
        }
        if (lane < NW) supw[lane] = sup;
    }
    __syncthreads();

    if (tid < 32) {                                    // compact kept, cap DET
        int outc = 0;
        for (int base = 0; base < nn; base += 32) {
            int i = base + lane;
            bool kept = (i < nn) && !((supw[i >> 5] >> (i & 31)) & 1);
            unsigned bal = __ballot_sync(0xffffffff, kept);
            int pos = outc + __popc(bal & ((1u << lane) - 1));
            if (kept && pos < DET) {
                g_kept[c * DET + pos] = buf[i];
                g_keptBox[c * DET + pos] = make_float4(X1[i], Y1[i], X2[i], Y2[i]);
            }
            outc += __popc(bal);
        }
        if (lane == 0) g_keptCnt[c] = min(outc, DET);
    }
}

// ---------------- K5: parallel merge via sort of kept entries ----------------
// key = score<<32 | (31-class)<<8 | (255-pos): desc sort == (score desc,
// class asc, in-class pos asc) == reference stable argsort order.
__global__ void __launch_bounds__(1024) k_out(float* __restrict__ out, int out_size) {
    __shared__ unsigned long long skeys[SEL_CAP];      // 32KB (4096 >= 20*200)
    __shared__ int cnts[NCLS];
    int tid = threadIdx.x;
    for (int t = tid; t < out_size; t += blockDim.x) out[t] = 0.f;
    if (tid < NCLS) cnts[tid] = g_keptCnt[tid];
    __syncthreads();
    for (int t = tid; t < SEL_CAP; t += blockDim.x) {
        unsigned long long key = 0ull;
        if (t < NCLS * DET) {
            int c = t / DET, pos = t % DET;
            if (pos < cnts[c]) {
                unsigned sb = (unsigned)(g_kept[c * DET + pos] >> 32);
                key = ((unsigned long long)sb << 32) |
                      ((unsigned)(31 - c) << 8) | (unsigned)(255 - pos);
            }
        }
        skeys[t] = key;
    }
    __syncthreads();
    bitonic_desc(skeys, SEL_CAP);

    for (int k = tid; k < DET; k += blockDim.x) {
        unsigned long long key = skeys[k];
        unsigned sb = (unsigned)(key >> 32);
        if (sb == 0) continue;                         // out already zeroed
        unsigned low = (unsigned)(key & 0xFFFFFFFFull);
        int c = 31 - (int)((low >> 8) & 0xFF);
        int pos = 255 - (int)(low & 0xFF);
        float4 bx = g_keptBox[c * DET + pos];
        *(float4*)(out + (size_t)k * 4) = bx;
        out[800 + k]  = __uint_as_float(sb);
        out[1000 + k] = (float)(c + 1);
    }
}

// ---------------- launch ------------------------------------------------------
extern "C" void kernel_launch(void* const* d_in, const int* in_sizes, int n_in,
                              void* d_out, int out_size) {
    const float* logits = (const float*)d_in[0];   // [A,21]
    const float* reg    = (const float*)d_in[1];   // [A,4]
    const float* anc    = (const float*)d_in[2];   // [A,4]
    float* out = (float*)d_out;

    k_prep<<<(AN / 4 + 255) / 256, 256>>>(logits);
    k_cut<<<1, 256>>>();
    k_scanexact<<<(AN + 255) / 256, 256>>>(logits);
    k_sortnms<<<NCLS, 1024>>>(reg, anc);           // launch #4 -> ncu target
    k_out<<<1, 1024>>>(out, out_size);
}

// round 10
// speedup vs baseline: 1.7574x; 1.7574x over previous
#include <cuda_runtime.h>
#include <cstdint>

#define AN 200000
#define NCLS 20          // foreground classes (labels 1..20)
#define NBIN 256         // log-domain histogram bins
#define TOPK 400
#define TOPKP 416        // TOPK padded to word boundary (13*32)
#define SEL_CAP 4096
#define DET 200
#define NW 13            // ceil(TOPK/32)
#define NMS_T 0.45f
#define K2E 1.44269504088896f

// ---------------- scratch (static device globals; no allocation) -------------
__device__ unsigned           g_binsP[AN * 8];          // 20 bin bytes/anchor, 32B stride
__device__ int                g_hist[NCLS * NBIN];
__device__ int                g_cut[NCLS];              // widened cutoff bin (>=1)
__device__ unsigned           g_cutPack[5];             // cut bytes packed like bins
__device__ unsigned long long g_sel[NCLS * SEL_CAP];    // EXACT keys (scorebits<<32)|(~idx)
__device__ int                g_selCnt[NCLS];
__device__ int                g_nmsN[NCLS];
__device__ float4             g_nmsBox[NCLS * TOPKP];   // decoded boxes of top-400
__device__ unsigned           g_mask[NCLS * TOPKP * NW];// suppression bitmatrix
__device__ unsigned long long g_kept[NCLS * DET];       // compacted post-NMS keys
__device__ float4             g_keptBox[NCLS * DET];
__device__ int                g_keptCnt[NCLS];

// ---------------- K1: log-domain bins + block-private histogram --------------
// bin = clamp((int)fmaf(log2(score), 38.2, 255.4), 0, 255); score 0.0099 -> ~1.
__global__ void __launch_bounds__(256) k_prep(const float* __restrict__ logits) {
    __shared__ int h[NCLS * NBIN];                     // 20KB private histogram
    int tid = threadIdx.x;
    for (int t = tid; t < NCLS * NBIN; t += 256) h[t] = 0;
    __syncthreads();

    int q = blockIdx.x * 256 + tid;                    // quad of 4 anchors
    if (q < AN / 4) {
        const float4* src = (const float4*)logits + (size_t)q * 21;  // 84 floats
        float S[4] = {0.f, 0.f, 0.f, 0.f};
#pragma unroll
        for (int k = 0; k < 21; k++) {
            float4 v = src[k];
            S[(4 * k + 0) / 21] += exp2f(v.x * K2E);
            S[(4 * k + 1) / 21] += exp2f(v.y * K2E);
            S[(4 * k + 2) / 21] += exp2f(v.z * K2E);
            S[(4 * k + 3) / 21] += exp2f(v.w * K2E);
        }
        float lg[4];
#pragma unroll
        for (int a = 0; a < 4; a++) lg[a] = __log2f(S[a]);

        unsigned w[20];
#pragma unroll
        for (int t = 0; t < 20; t++) w[t] = 0;
#pragma unroll
        for (int k = 0; k < 21; k++) {
            float4 v = src[k];                          // L1 hit (2nd pass)
            float e[4] = {v.x, v.y, v.z, v.w};
#pragma unroll
            for (int j = 0; j < 4; j++) {
                int f = 4 * k + j, a = f / 21, c = f % 21;
                if (c >= 1) {
                    int cc = c - 1;
                    float y = fmaf(e[j], K2E, -lg[a]);
                    int bin = (int)fmaf(y, 38.2f, 255.4f);
                    bin = max(0, min(255, bin));
                    if (bin > 0) atomicAdd(&h[cc * NBIN + bin], 1);
                    w[a * 5 + (cc >> 2)] |= (unsigned)bin << ((cc & 3) * 8);
                }
            }
        }
#pragma unroll
        for (int a = 0; a < 4; a++) {
            unsigned i = (unsigned)(q * 4 + a);
            *(uint4*)&g_binsP[(size_t)i * 8] =
                make_uint4(w[a * 5], w[a * 5 + 1], w[a * 5 + 2], w[a * 5 + 3]);
            g_binsP[(size_t)i * 8 + 4] = w[a * 5 + 4];
        }
    }
    __syncthreads();
    for (int t = tid; t < NCLS * NBIN; t += 256) {
        int v = h[t];
        if (v) atomicAdd(&g_hist[t], v);
    }
}

// ---------------- K2: widened rank-400 cutoff; then reset state --------------
__global__ void k_cut() {
    int tid = threadIdx.x, wid = tid >> 5, lane = tid & 31;
    for (int c = wid; c < NCLS; c += 8) {
        int cum = 0, cutbin = 1;
        bool found = false;
        for (int base = NBIN - 32; base >= 0; base -= 32) {
            int b = base + 31 - lane;                 // lane 0 = highest bin
            int v = g_hist[c * NBIN + b];
            int s = v;
#pragma unroll
            for (int off = 1; off < 32; off <<= 1) {
                int t = __shfl_up_sync(0xffffffffu, s, off);
                if (lane >= off) s += t;
            }
            unsigned bal = __ballot_sync(0xffffffffu, (cum + s) >= TOPK);
            int tot = __shfl_sync(0xffffffffu, s, 31);
            if (bal) {
                cutbin = base + 31 - (__ffs(bal) - 1);
                found = true;
                break;
            }
            cum += tot;
        }
        // widen by 1 bin: approx-score error (~1e-6) vs bin width (~1.8%) margin
        if (lane == 0) g_cut[c] = found ? max(cutbin - 1, 1) : 1;
    }
    __syncthreads();
    // reset for the NEXT call; selCnt consumed later in THIS call
    for (int t = tid; t < NCLS * NBIN; t += 256) g_hist[t] = 0;
    if (tid < NCLS) g_selCnt[tid] = 0;
    __syncthreads();
    if (tid < 5) {
        unsigned p = 0;
#pragma unroll
        for (int j = 0; j < 4; j++) {
            int c = tid * 4 + j;
            unsigned cv = (c < NCLS) ? (unsigned)g_cut[c] : 255u;
            p |= (cv & 255u) << (j * 8);
        }
        g_cutPack[tid] = p;
    }
}

// ---------------- K3: fused scan + exact rescoring (full parallelism) --------
__global__ void __launch_bounds__(256) k_scanexact(const float* __restrict__ logits) {
    __shared__ unsigned cp[5];
    __shared__ int scut[NCLS];
    if (threadIdx.x < 5) cp[threadIdx.x] = g_cutPack[threadIdx.x];
    if (threadIdx.x < NCLS) scut[threadIdx.x] = g_cut[threadIdx.x];
    __syncthreads();
    int i = blockIdx.x * 256 + threadIdx.x;
    if (i >= AN) return;
    uint4 b4 = *(const uint4*)&g_binsP[(size_t)i * 8];
    unsigned b5 = g_binsP[(size_t)i * 8 + 4];
    unsigned any = __vsetgeu4(b4.x, cp[0]) | __vsetgeu4(b4.y, cp[1]) |
                   __vsetgeu4(b4.z, cp[2]) | __vsetgeu4(b4.w, cp[3]) |
                   __vsetgeu4(b5, cp[4]);
    if (!any) return;

    unsigned wv[5] = {b4.x, b4.y, b4.z, b4.w, b5};
    // exact softmax pieces (accurate expf, div.rn) — matches reference path
    const float* L = logits + (size_t)i * 21;
    float Lr[21];
#pragma unroll
    for (int c = 0; c < 21; c++) Lr[c] = L[c];
    float m = Lr[0];
#pragma unroll
    for (int c = 1; c < 21; c++) m = fmaxf(m, Lr[c]);
    float S = 0.f;
#pragma unroll
    for (int c = 0; c < 21; c++) S += expf(Lr[c] - m);

#pragma unroll
    for (int c = 0; c < NCLS; c++) {
        int b = (wv[c >> 2] >> ((c & 3) * 8)) & 255;
        if (b < scut[c]) continue;
        float ex = expf(Lr[c + 1] - m) / S;            // exact, matches reference
        if (ex <= 0.01f) continue;
        unsigned long long key =
            ((unsigned long long)__float_as_uint(ex) << 32) | (0xFFFFFFFFu - (unsigned)i);
        int p = atomicAdd(&g_selCnt[c], 1);
        if (p < SEL_CAP) g_sel[c * SEL_CAP + p] = key;
    }
}

// ---------------- bitonic sort (descending) in shared ------------------------
__device__ void bitonic_desc(unsigned long long* buf, int np2) {
    int tid = threadIdx.x, bd = blockDim.x;
    for (int k = 2; k <= np2; k <<= 1) {
        for (int j = k >> 1; j > 0; j >>= 1) {
            for (int t = tid; t < np2; t += bd) {
                int ixj = t ^ j;
                if (ixj > t) {
                    unsigned long long a = buf[t], b = buf[ixj];
                    bool desc = ((t & k) == 0);
                    if ((a < b) == desc) { buf[t] = b; buf[ixj] = a; }
                }
            }
            __syncthreads();
        }
    }
}

// ---------------- K4: per-class sort + decode top-400 ------------------------
__global__ void __launch_bounds__(1024) k_sort(const float* __restrict__ reg,
                                               const float* __restrict__ anc) {
    __shared__ unsigned long long buf[SEL_CAP];        // 32KB
    int c = blockIdx.x, tid = threadIdx.x;
    int n = min(g_selCnt[c], SEL_CAP);
    int np2 = 2; while (np2 < n) np2 <<= 1;
    for (int t = tid; t < np2; t += blockDim.x)
        buf[t] = (t < n) ? g_sel[c * SEL_CAP + t] : 0ull;
    __syncthreads();
    bitonic_desc(buf, np2);
    int nn = min(n, TOPK);
    if (tid == 0) g_nmsN[c] = nn;

    // write sorted top keys back; decode boxes (pad with degenerate zeros)
    for (int t = tid; t < TOPKP; t += blockDim.x) {
        if (t < nn) {
            unsigned long long key = buf[t];
            g_sel[c * SEL_CAP + t] = key;
            unsigned idx = 0xFFFFFFFFu - (unsigned)(key & 0xFFFFFFFFull);
            float4 a4 = *(const float4*)(anc + (size_t)idx * 4);
            float4 r4 = *(const float4*)(reg + (size_t)idx * 4);
            float aw = a4.z - a4.x, ah = a4.w - a4.y;
            float acx = a4.x + 0.5f * aw, acy = a4.y + 0.5f * ah;
            float dx = r4.x / 10.0f, dy = r4.y / 10.0f;
            float dw = fminf(r4.z / 5.0f, 4.135166556742356f);
            float dh = fminf(r4.w / 5.0f, 4.135166556742356f);
            float pcx = dx * aw + acx, pcy = dy * ah + acy;
            float pw = expf(dw) * aw, ph = expf(dh) * ah;
            float4 b4;
            b4.x = fminf(fmaxf(pcx - 0.5f * pw, 0.f), 320.f);
            b4.y = fminf(fmaxf(pcy - 0.5f * ph, 0.f), 320.f);
            b4.z = fminf(fmaxf(pcx + 0.5f * pw, 0.f), 320.f);
            b4.w = fminf(fmaxf(pcy + 0.5f * ph, 0.f), 320.f);
            g_nmsBox[c * TOPKP + t] = b4;
        } else {
            g_nmsBox[c * TOPKP + t] = make_float4(0.f, 0.f, 0.f, 0.f);
        }
    }
}

// ---------------- K5: mask build; block (w, c) = one word column -------------
// All threads read the SAME j each step -> broadcast LDS, conflict-free.
__global__ void __launch_bounds__(TOPKP) k_mask() {
    __shared__ float X1[TOPKP], Y1[TOPKP], X2[TOPKP], Y2[TOPKP], AR[TOPKP];
    int w = blockIdx.x, c = blockIdx.y;
    int i = threadIdx.x;                               // row (0..415)
    float4 b4 = g_nmsBox[c * TOPKP + i];
    X1[i] = b4.x; Y1[i] = b4.y; X2[i] = b4.z; Y2[i] = b4.w;
    AR[i] = (b4.z - b4.x) * (b4.w - b4.y);
    __syncthreads();

    int jbase = w << 5;
    unsigned m = 0;
    if (jbase + 31 > i) {                              // word touches j>i region
        float xi1 = X1[i], yi1 = Y1[i], xi2 = X2[i], yi2 = Y2[i], ai = AR[i];
#pragma unroll
        for (int b = 0; b < 32; b++) {                 // pad rows give iou=NaN/0 -> false
            int j = jbase + b;
            float lx = fmaxf(xi1, X1[j]), ly = fmaxf(yi1, Y1[j]);
            float rx = fminf(xi2, X2[j]), ry = fminf(yi2, Y2[j]);
            float ww = fmaxf(rx - lx, 0.f), hh = fmaxf(ry - ly, 0.f);
            float inter = ww * hh;
            float iou = inter / (ai + AR[j] - inter);   // div.rn; NaN>T==false
            if (iou > NMS_T) m |= (1u << b);
        }
        if (i >= jbase)                                // clear diagonal + below bits
            m &= ~(((i - jbase) >= 31) ? 0xFFFFFFFFu : ((2u << (i - jbase)) - 1u));
    }
    g_mask[(c * TOPKP + i) * NW + w] = m;
}

// ---------------- K6: greedy sweep + compact ---------------------------------
__global__ void __launch_bounds__(512) k_sweep() {
    __shared__ unsigned mask[TOPK * NW];               // 20.8KB
    __shared__ unsigned supw[NW];
    int c = blockIdx.x, tid = threadIdx.x, lane = tid & 31;
    int nn = g_nmsN[c];
    for (int t = tid; t < nn * NW; t += blockDim.x)
        mask[t] = g_mask[(c * TOPKP + t / NW) * NW + (t % NW)];
    __syncthreads();

    int nw_used = (nn + 31) >> 5;
    if (tid < 32) {                                    // serial greedy sweep, prefetched
        unsigned sup = 0;
        bool act = (lane < nw_used);
        unsigned cur = (act && nn > 0) ? mask[lane] : 0u;
        for (int i = 0; i < nn; i++) {
            unsigned nxt = (act && i + 1 < nn) ? mask[(i + 1) * NW + lane] : 0u;
            unsigned wi = __shfl_sync(0xffffffff, sup, i >> 5);
            if (!((wi >> (i & 31)) & 1)) sup |= cur;
            cur = nxt;
        }
        if (lane < NW) supw[lane] = sup;
    }
    __syncthreads();

    if (tid < 32) {                                    // compact kept, cap DET
        int outc = 0;
        for (int base = 0; base < nn; base += 32) {
            int i = base + lane;
            bool kept = (i < nn) && !((supw[i >> 5] >> (i & 31)) & 1);
            unsigned bal = __ballot_sync(0xffffffff, kept);
            int pos = outc + __popc(bal & ((1u << lane) - 1));
            if (kept && pos < DET) {
                g_kept[c * DET + pos] = g_sel[c * SEL_CAP + i];
                g_keptBox[c * DET + pos] = g_nmsBox[c * TOPKP + i];
            }
            outc += __popc(bal);
        }
        if (lane == 0) g_keptCnt[c] = min(outc, DET);
    }
}

// ---------------- K7: parallel merge via sort of kept entries ----------------
// key = score<<32 | (31-class)<<8 | (255-pos): desc sort == (score desc,
// class asc, in-class pos asc) == reference stable argsort order.
__global__ void __launch_bounds__(1024) k_out(float* __restrict__ out, int out_size) {
    __shared__ unsigned long long skeys[SEL_CAP];      // 32KB (4096 >= 20*200)
    __shared__ int cnts[NCLS];
    int tid = threadIdx.x;
    for (int t = tid; t < out_size; t += blockDim.x) out[t] = 0.f;
    if (tid < NCLS) cnts[tid] = g_keptCnt[tid];
    __syncthreads();
    for (int t = tid; t < SEL_CAP; t += blockDim.x) {
        unsigned long long key = 0ull;
        if (t < NCLS * DET) {
            int c = t / DET, pos = t % DET;
            if (pos < cnts[c]) {
                unsigned sb = (unsigned)(g_kept[c * DET + pos] >> 32);
                key = ((unsigned long long)sb << 32) |
                      ((unsigned)(31 - c) << 8) | (unsigned)(255 - pos);
            }
        }
        skeys[t] = key;
    }
    __syncthreads();
    bitonic_desc(skeys, SEL_CAP);

    for (int k = tid; k < DET; k += blockDim.x) {
        unsigned long long key = skeys[k];
        unsigned sb = (unsigned)(key >> 32);
        if (sb == 0) continue;                         // out already zeroed
        unsigned low = (unsigned)(key & 0xFFFFFFFFull);
        int c = 31 - (int)((low >> 8) & 0xFF);
        int pos = 255 - (int)(low & 0xFF);
        float4 bx = g_keptBox[c * DET + pos];
        *(float4*)(out + (size_t)k * 4) = bx;
        out[800 + k]  = __uint_as_float(sb);
        out[1000 + k] = (float)(c + 1);
    }
}

// ---------------- launch ------------------------------------------------------
extern "C" void kernel_launch(void* const* d_in, const int* in_sizes, int n_in,
                              void* d_out, int out_size) {
    const float* logits = (const float*)d_in[0];   // [A,21]
    const float* reg    = (const float*)d_in[1];   // [A,4]
    const float* anc    = (const float*)d_in[2];   // [A,4]
    float* out = (float*)d_out;

    k_prep<<<(AN / 4 + 255) / 256, 256>>>(logits);
    k_cut<<<1, 256>>>();
    k_scanexact<<<(AN + 255) / 256, 256>>>(logits);
    k_sort<<<NCLS, 1024>>>(reg, anc);
    k_mask<<<dim3(NW, NCLS), TOPKP>>>();
    k_sweep<<<NCLS, 512>>>();
    k_out<<<1, 1024>>>(out, out_size);
}

// round 11
// speedup vs baseline: 1.8906x; 1.0758x over previous
#include <cuda_runtime.h>
#include <cstdint>

#define AN 200000
#define NCLS 20          // foreground classes (labels 1..20)
#define NBIN 256         // log-domain histogram bins
#define TOPK 400
#define TOPKP 416        // TOPK padded to word boundary (13*32)
#define SEL_CAP 4096
#define DET 200
#define NW 13            // ceil(TOPK/32)
#define NMS_T 0.45f
#define K2E 1.44269504088896f

// ---------------- scratch (static device globals; no allocation) -------------
__device__ unsigned           g_binsP[AN * 8];          // 20 bin bytes/anchor, 32B stride
__device__ int                g_hist[NCLS * NBIN];
__device__ int                g_cut[NCLS];              // widened cutoff bin (>=1)
__device__ unsigned           g_cutPack[5];             // cut bytes packed like bins
__device__ unsigned long long g_sel[NCLS * SEL_CAP];    // EXACT keys (scorebits<<32)|(~idx)
__device__ int                g_selCnt[NCLS];
__device__ int                g_nmsN[NCLS];
__device__ float4             g_nmsBox[NCLS * TOPKP];   // decoded boxes of top-400
__device__ unsigned           g_mask[NCLS * TOPKP * NW];// suppression bitmatrix
__device__ unsigned long long g_kept[NCLS * DET];       // compacted post-NMS keys
__device__ float4             g_keptBox[NCLS * DET];
__device__ int                g_keptCnt[NCLS];

// ---------------- K1: log-domain bins + block-private histogram --------------
// bin = clamp((int)fmaf(log2(score), 38.2, 255.4), 0, 255); score 0.0099 -> ~1.
__global__ void __launch_bounds__(256) k_prep(const float* __restrict__ logits) {
    __shared__ int h[NCLS * NBIN];                     // 20KB private histogram
    int tid = threadIdx.x;
    for (int t = tid; t < NCLS * NBIN; t += 256) h[t] = 0;
    __syncthreads();

    int q = blockIdx.x * 256 + tid;                    // quad of 4 anchors
    if (q < AN / 4) {
        const float4* src = (const float4*)logits + (size_t)q * 21;  // 84 floats
        float S[4] = {0.f, 0.f, 0.f, 0.f};
#pragma unroll
        for (int k = 0; k < 21; k++) {
            float4 v = src[k];
            S[(4 * k + 0) / 21] += exp2f(v.x * K2E);
            S[(4 * k + 1) / 21] += exp2f(v.y * K2E);
            S[(4 * k + 2) / 21] += exp2f(v.z * K2E);
            S[(4 * k + 3) / 21] += exp2f(v.w * K2E);
        }
        float lg[4];
#pragma unroll
        for (int a = 0; a < 4; a++) lg[a] = __log2f(S[a]);

        unsigned w[20];
#pragma unroll
        for (int t = 0; t < 20; t++) w[t] = 0;
#pragma unroll
        for (int k = 0; k < 21; k++) {
            float4 v = src[k];                          // L1 hit (2nd pass)
            float e[4] = {v.x, v.y, v.z, v.w};
#pragma unroll
            for (int j = 0; j < 4; j++) {
                int f = 4 * k + j, a = f / 21, c = f % 21;
                if (c >= 1) {
                    int cc = c - 1;
                    float y = fmaf(e[j], K2E, -lg[a]);
                    int bin = (int)fmaf(y, 38.2f, 255.4f);
                    bin = max(0, min(255, bin));
                    if (bin > 0) atomicAdd(&h[cc * NBIN + bin], 1);
                    w[a * 5 + (cc >> 2)] |= (unsigned)bin << ((cc & 3) * 8);
                }
            }
        }
#pragma unroll
        for (int a = 0; a < 4; a++) {
            unsigned i = (unsigned)(q * 4 + a);
            *(uint4*)&g_binsP[(size_t)i * 8] =
                make_uint4(w[a * 5], w[a * 5 + 1], w[a * 5 + 2], w[a * 5 + 3]);
            g_binsP[(size_t)i * 8 + 4] = w[a * 5 + 4];
        }
    }
    __syncthreads();
    for (int t = tid; t < NCLS * NBIN; t += 256) {
        int v = h[t];
        if (v) atomicAdd(&g_hist[t], v);
    }
}

// ---------------- K2: widened rank-400 cutoff; then reset state --------------
__global__ void k_cut() {
    int tid = threadIdx.x, wid = tid >> 5, lane = tid & 31;
    for (int c = wid; c < NCLS; c += 8) {
        int cum = 0, cutbin = 1;
        bool found = false;
        for (int base = NBIN - 32; base >= 0; base -= 32) {
            int b = base + 31 - lane;                 // lane 0 = highest bin
            int v = g_hist[c * NBIN + b];
            int s = v;
#pragma unroll
            for (int off = 1; off < 32; off <<= 1) {
                int t = __shfl_up_sync(0xffffffffu, s, off);
                if (lane >= off) s += t;
            }
            unsigned bal = __ballot_sync(0xffffffffu, (cum + s) >= TOPK);
            int tot = __shfl_sync(0xffffffffu, s, 31);
            if (bal) {
                cutbin = base + 31 - (__ffs(bal) - 1);
                found = true;
                break;
            }
            cum += tot;
        }
        // widen by 1 bin: approx-score error (~1e-6) vs bin width (~1.8%) margin
        if (lane == 0) g_cut[c] = found ? max(cutbin - 1, 1) : 1;
    }
    __syncthreads();
    // reset for the NEXT call; selCnt consumed later in THIS call
    for (int t = tid; t < NCLS * NBIN; t += 256) g_hist[t] = 0;
    if (tid < NCLS) g_selCnt[tid] = 0;
    __syncthreads();
    if (tid < 5) {
        unsigned p = 0;
#pragma unroll
        for (int j = 0; j < 4; j++) {
            int c = tid * 4 + j;
            unsigned cv = (c < NCLS) ? (unsigned)g_cut[c] : 255u;
            p |= (cv & 255u) << (j * 8);
        }
        g_cutPack[tid] = p;
    }
}

// ---------------- K3: fused scan + exact rescoring (full parallelism) --------
__global__ void __launch_bounds__(256) k_scanexact(const float* __restrict__ logits) {
    __shared__ unsigned cp[5];
    __shared__ int scut[NCLS];
    if (threadIdx.x < 5) cp[threadIdx.x] = g_cutPack[threadIdx.x];
    if (threadIdx.x < NCLS) scut[threadIdx.x] = g_cut[threadIdx.x];
    __syncthreads();
    int i = blockIdx.x * 256 + threadIdx.x;
    if (i >= AN) return;
    uint4 b4 = *(const uint4*)&g_binsP[(size_t)i * 8];
    unsigned b5 = g_binsP[(size_t)i * 8 + 4];
    unsigned any = __vsetgeu4(b4.x, cp[0]) | __vsetgeu4(b4.y, cp[1]) |
                   __vsetgeu4(b4.z, cp[2]) | __vsetgeu4(b4.w, cp[3]) |
                   __vsetgeu4(b5, cp[4]);
    if (!any) return;

    unsigned wv[5] = {b4.x, b4.y, b4.z, b4.w, b5};
    // exact softmax pieces (accurate expf, div.rn) — matches reference path
    const float* L = logits + (size_t)i * 21;
    float Lr[21];
#pragma unroll
    for (int c = 0; c < 21; c++) Lr[c] = L[c];
    float m = Lr[0];
#pragma unroll
    for (int c = 1; c < 21; c++) m = fmaxf(m, Lr[c]);
    float S = 0.f;
#pragma unroll
    for (int c = 0; c < 21; c++) S += expf(Lr[c] - m);

#pragma unroll
    for (int c = 0; c < NCLS; c++) {
        int b = (wv[c >> 2] >> ((c & 3) * 8)) & 255;
        if (b < scut[c]) continue;
        float ex = expf(Lr[c + 1] - m) / S;            // exact, matches reference
        if (ex <= 0.01f) continue;
        unsigned long long key =
            ((unsigned long long)__float_as_uint(ex) << 32) | (0xFFFFFFFFu - (unsigned)i);
        int p = atomicAdd(&g_selCnt[c], 1);
        if (p < SEL_CAP) g_sel[c * SEL_CAP + p] = key;
    }
}

// ---------------- bitonic sorts (descending) ---------------------------------
// generic shared-memory version (fallback, np2 may exceed blockDim)
__device__ void bitonic_desc(unsigned long long* buf, int np2) {
    int tid = threadIdx.x, bd = blockDim.x;
    for (int k = 2; k <= np2; k <<= 1) {
        for (int j = k >> 1; j > 0; j >>= 1) {
            for (int t = tid; t < np2; t += bd) {
                int ixj = t ^ j;
                if (ixj > t) {
                    unsigned long long a = buf[t], b = buf[ixj];
                    bool desc = ((t & k) == 0);
                    if ((a < b) == desc) { buf[t] = b; buf[ixj] = a; }
                }
            }
            __syncthreads();
        }
    }
}

// register/hybrid version: one element per thread, np2 <= blockDim.
// j<=16 phases via shfl (no barrier); j>=32 phases via shared exchange.
__device__ unsigned long long bitonic_reg_desc(unsigned long long v,
                                               unsigned long long* sm, int np2) {
    int t = threadIdx.x;
    for (int k = 2; k <= np2; k <<= 1) {
        bool up = ((t & k) == 0);                      // descending region
        for (int j = k >> 1; j >= 32; j >>= 1) {
            sm[t] = v;
            __syncthreads();
            unsigned long long p = sm[t ^ j];
            __syncthreads();
            bool lower = ((t & j) == 0);
            bool keepMax = (up == lower);
            v = keepMax ? (v > p ? v : p) : (v < p ? v : p);
        }
        int jmax = min(k >> 1, 16);
        for (int j = jmax; j >= 1; j >>= 1) {
            unsigned long long p = __shfl_xor_sync(0xffffffffu, v, j);
            bool lower = ((t & j) == 0);
            bool keepMax = (up == lower);
            v = keepMax ? (v > p ? v : p) : (v < p ? v : p);
        }
    }
    return v;
}

// ---------------- K4: per-class sort + decode top-400 ------------------------
__global__ void __launch_bounds__(1024) k_sort(const float* __restrict__ reg,
                                               const float* __restrict__ anc) {
    __shared__ unsigned long long buf[SEL_CAP];        // 32KB
    int c = blockIdx.x, tid = threadIdx.x;
    int n = min(g_selCnt[c], SEL_CAP);
    int np2 = 2; while (np2 < n) np2 <<= 1;

    if (np2 <= 1024) {                                 // fast hybrid path
        unsigned long long v = (tid < n) ? g_sel[c * SEL_CAP + tid] : 0ull;
        v = bitonic_reg_desc(v, buf, np2);
        buf[tid] = v;
        __syncthreads();
    } else {                                           // fallback (rare)
        for (int t = tid; t < np2; t += blockDim.x)
            buf[t] = (t < n) ? g_sel[c * SEL_CAP + t] : 0ull;
        __syncthreads();
        bitonic_desc(buf, np2);
    }
    int nn = min(n, TOPK);
    if (tid == 0) g_nmsN[c] = nn;

    // write sorted top keys back; decode boxes (pad with degenerate zeros)
    for (int t = tid; t < TOPKP; t += blockDim.x) {
        if (t < nn) {
            unsigned long long key = buf[t];
            g_sel[c * SEL_CAP + t] = key;
            unsigned idx = 0xFFFFFFFFu - (unsigned)(key & 0xFFFFFFFFull);
            float4 a4 = *(const float4*)(anc + (size_t)idx * 4);
            float4 r4 = *(const float4*)(reg + (size_t)idx * 4);
            float aw = a4.z - a4.x, ah = a4.w - a4.y;
            float acx = a4.x + 0.5f * aw, acy = a4.y + 0.5f * ah;
            float dx = r4.x / 10.0f, dy = r4.y / 10.0f;
            float dw = fminf(r4.z / 5.0f, 4.135166556742356f);
            float dh = fminf(r4.w / 5.0f, 4.135166556742356f);
            float pcx = dx * aw + acx, pcy = dy * ah + acy;
            float pw = expf(dw) * aw, ph = expf(dh) * ah;
            float4 b4;
            b4.x = fminf(fmaxf(pcx - 0.5f * pw, 0.f), 320.f);
            b4.y = fminf(fmaxf(pcy - 0.5f * ph, 0.f), 320.f);
            b4.z = fminf(fmaxf(pcx + 0.5f * pw, 0.f), 320.f);
            b4.w = fminf(fmaxf(pcy + 0.5f * ph, 0.f), 320.f);
            g_nmsBox[c * TOPKP + t] = b4;
        } else {
            g_nmsBox[c * TOPKP + t] = make_float4(0.f, 0.f, 0.f, 0.f);
        }
    }
}

// ---------------- K5: mask build; block (w, c) = one word column -------------
// All threads read the SAME j each step -> broadcast LDS, conflict-free.
__global__ void __launch_bounds__(TOPKP) k_mask() {
    __shared__ float X1[TOPKP], Y1[TOPKP], X2[TOPKP], Y2[TOPKP], AR[TOPKP];
    int w = blockIdx.x, c = blockIdx.y;
    int i = threadIdx.x;                               // row (0..415)
    float4 b4 = g_nmsBox[c * TOPKP + i];
    X1[i] = b4.x; Y1[i] = b4.y; X2[i] = b4.z; Y2[i] = b4.w;
    AR[i] = (b4.z - b4.x) * (b4.w - b4.y);
    __syncthreads();

    int jbase = w << 5;
    unsigned m = 0;
    if (jbase + 31 > i) {                              // word touches j>i region
        float xi1 = X1[i], yi1 = Y1[i], xi2 = X2[i], yi2 = Y2[i], ai = AR[i];
#pragma unroll
        for (int b = 0; b < 32; b++) {                 // pad rows give iou=NaN/0 -> false
            int j = jbase + b;
            float lx = fmaxf(xi1, X1[j]), ly = fmaxf(yi1, Y1[j]);
            float rx = fminf(xi2, X2[j]), ry = fminf(yi2, Y2[j]);
            float ww = fmaxf(rx - lx, 0.f), hh = fmaxf(ry - ly, 0.f);
            float inter = ww * hh;
            float iou = inter / (ai + AR[j] - inter);   // div.rn; NaN>T==false
            if (iou > NMS_T) m |= (1u << b);
        }
        if (i >= jbase)                                // clear diagonal + below bits
            m &= ~(((i - jbase) >= 31) ? 0xFFFFFFFFu : ((2u << (i - jbase)) - 1u));
    }
    g_mask[(c * TOPKP + i) * NW + w] = m;
}

// ---------------- K6: greedy sweep (short chain) + compact -------------------
__global__ void __launch_bounds__(512) k_sweep() {
    __shared__ unsigned mask[TOPK * NW];               // 20.8KB
    __shared__ unsigned supw[NW];
    int c = blockIdx.x, tid = threadIdx.x, lane = tid & 31;
    int nn = g_nmsN[c];
    for (int t = tid; t < nn * NW; t += blockDim.x)
        mask[t] = g_mask[(c * TOPKP + t / NW) * NW + (t % NW)];
    __syncthreads();

    int nw_used = (nn + 31) >> 5;
    if (tid < 32) {
        unsigned sup = 0;                              // lane l owns sup word l
        for (int chunk = 0; chunk < nw_used; chunk++) {
            unsigned supc = __shfl_sync(0xffffffffu, sup, chunk); // local copy
            int i0 = chunk << 5, iend = min(nn, i0 + 32);
            for (int i = i0; i < iend; i++) {
                unsigned mrow_l = (lane < nw_used) ? mask[i * NW + lane] : 0u;
                unsigned mrow_c = mask[i * NW + chunk];  // broadcast
                if (!((supc >> (i & 31)) & 1)) {         // row i alive
                    sup |= mrow_l;
                    supc |= mrow_c;                      // 4-cyc serial chain
                }
            }
        }
        if (lane < NW) supw[lane] = sup;
    }
    __syncthreads();

    if (tid < 32) {                                    // compact kept, cap DET
        int outc = 0;
        for (int base = 0; base < nn; base += 32) {
            int i = base + lane;
            bool kept = (i < nn) && !((supw[i >> 5] >> (i & 31)) & 1);
            unsigned bal = __ballot_sync(0xffffffff, kept);
            int pos = outc + __popc(bal & ((1u << lane) - 1));
            if (kept && pos < DET) {
                g_kept[c * DET + pos] = g_sel[c * SEL_CAP + i];
                g_keptBox[c * DET + pos] = g_nmsBox[c * TOPKP + i];
            }
            outc += __popc(bal);
        }
        if (lane == 0) g_keptCnt[c] = min(outc, DET);
    }
}

// ---------------- K7: merge via compacted sort of kept entries ---------------
// key = score<<32 | (31-class)<<8 | (255-pos): desc sort == (score desc,
// class asc, in-class pos asc) == reference stable argsort order.
__global__ void __launch_bounds__(1024) k_out(float* __restrict__ out, int out_size) {
    __shared__ unsigned long long skeys[SEL_CAP];      // 32KB
    __shared__ int cnts[NCLS];
    __shared__ int offs[NCLS + 1];
    int tid = threadIdx.x;
    for (int t = tid; t < out_size; t += blockDim.x) out[t] = 0.f;
    if (tid < NCLS) cnts[tid] = g_keptCnt[tid];
    __syncthreads();
    if (tid == 0) {
        int a = 0;
        for (int c = 0; c < NCLS; c++) { offs[c] = a; a += cnts[c]; }
        offs[NCLS] = a;
    }
    __syncthreads();
    int total = offs[NCLS];
    int np2 = 2; while (np2 < total) np2 <<= 1;

    for (int t = tid; t < np2; t += blockDim.x) skeys[t] = 0ull;
    __syncthreads();
    for (int t = tid; t < NCLS * DET; t += blockDim.x) {
        int c = t / DET, pos = t % DET;
        if (pos < cnts[c]) {
            unsigned sb = (unsigned)(g_kept[c * DET + pos] >> 32);
            skeys[offs[c] + pos] = ((unsigned long long)sb << 32) |
                                   ((unsigned)(31 - c) << 8) | (unsigned)(255 - pos);
        }
    }
    __syncthreads();

    if (np2 <= 1024) {                                 // fast hybrid path
        unsigned long long v = skeys[tid];
        v = bitonic_reg_desc(v, skeys, np2);
        __syncthreads();
        skeys[tid] = v;
        __syncthreads();
    } else {                                           // fallback (rare)
        bitonic_desc(skeys, np2);
    }

    for (int k = tid; k < DET; k += blockDim.x) {
        unsigned long long key = (k < np2) ? skeys[k] : 0ull;
        unsigned sb = (unsigned)(key >> 32);
        if (sb == 0) continue;                         // out already zeroed
        unsigned low = (unsigned)(key & 0xFFFFFFFFull);
        int c = 31 - (int)((low >> 8) & 0xFF);
        int pos = 255 - (int)(low & 0xFF);
        float4 bx = g_keptBox[c * DET + pos];
        *(float4*)(out + (size_t)k * 4) = bx;
        out[800 + k]  = __uint_as_float(sb);
        out[1000 + k] = (float)(c + 1);
    }
}

// ---------------- launch ------------------------------------------------------
extern "C" void kernel_launch(void* const* d_in, const int* in_sizes, int n_in,
                              void* d_out, int out_size) {
    const float* logits = (const float*)d_in[0];   // [A,21]
    const float* reg    = (const float*)d_in[1];   // [A,4]
    const float* anc    = (const float*)d_in[2];   // [A,4]
    float* out = (float*)d_out;

    k_prep<<<(AN / 4 + 255) / 256, 256>>>(logits);
    k_cut<<<1, 256>>>();
    k_scanexact<<<(AN + 255) / 256, 256>>>(logits);
    k_sort<<<NCLS, 1024>>>(reg, anc);              // launch #4 -> ncu target
    k_mask<<<dim3(NW, NCLS), TOPKP>>>();
    k_sweep<<<NCLS, 512>>>();
    k_out<<<1, 1024>>>(out, out_size);
}